// round 12
// baseline (speedup 1.0000x reference)
#include <cuda_runtime.h>
#include <cuda_bf16.h>
#include <cstdint>

// ST-BIF multi-step neuron, T=4 timesteps. HBM-bound streaming kernel.
// This round: 256-bit global accesses (ld/st.global.v8.b32, sm_100a+) --
// one thread owns 8 consecutive floats x 4 timesteps. Halves L1tex
// wavefronts and LTS request count per byte vs float4.

#define POS_MAX 15.0f
#define NEG_MIN 0.0f
#define TSTEPS  4

__device__ __forceinline__ float bif_step(float& v, float& tc, float xv, float vth) {
    float H = v + xv;
    float spike;
    if (H >= vth && tc < POS_MAX)      spike = 1.0f;
    else if (H < 0.0f && tc > NEG_MIN) spike = -1.0f;
    else                               spike = 0.0f;
    v  = H - spike * vth;
    tc = tc + spike;
    return spike * vth;
}

// 256-bit load: 8 consecutive b32 from global (requires 32B alignment).
__device__ __forceinline__ void ldg256(const float* p, float r[8]) {
    uint32_t u0, u1, u2, u3, u4, u5, u6, u7;
    asm volatile("ld.global.nc.v8.b32 {%0,%1,%2,%3,%4,%5,%6,%7}, [%8];"
                 : "=r"(u0), "=r"(u1), "=r"(u2), "=r"(u3),
                   "=r"(u4), "=r"(u5), "=r"(u6), "=r"(u7)
                 : "l"(p));
    r[0] = __uint_as_float(u0); r[1] = __uint_as_float(u1);
    r[2] = __uint_as_float(u2); r[3] = __uint_as_float(u3);
    r[4] = __uint_as_float(u4); r[5] = __uint_as_float(u5);
    r[6] = __uint_as_float(u6); r[7] = __uint_as_float(u7);
}

// 256-bit streaming store.
__device__ __forceinline__ void stg256(float* p, const float r[8]) {
    asm volatile("st.global.cs.v8.b32 [%0], {%1,%2,%3,%4,%5,%6,%7,%8};"
                 :: "l"(p),
                    "r"(__float_as_uint(r[0])), "r"(__float_as_uint(r[1])),
                    "r"(__float_as_uint(r[2])), "r"(__float_as_uint(r[3])),
                    "r"(__float_as_uint(r[4])), "r"(__float_as_uint(r[5])),
                    "r"(__float_as_uint(r[6])), "r"(__float_as_uint(r[7]))
                 : "memory");
}

__global__ void __launch_bounds__(256)
st_bif_ms_kernel(const float* __restrict__ x,
                 const float* __restrict__ qth_ptr,
                 float* __restrict__ out,
                 int stepN)  // elements per timestep (B*L*D)
{
    int idx = (blockIdx.x * blockDim.x + threadIdx.x) * 8;
    if (idx >= stepN) return;

    const float vth = __ldg(qth_ptr);

    // Front-batch all 4 timestep loads: 4 independent LDG.256 (32B each)
    float xs0[8], xs1[8], xs2[8], xs3[8];
    ldg256(x + idx,                      xs0);
    ldg256(x + idx + (size_t)stepN,      xs1);
    ldg256(x + idx + (size_t)2 * stepN,  xs2);
    ldg256(x + idx + (size_t)3 * stepN,  xs3);

    float v[8], tc[8];
    #pragma unroll
    for (int j = 0; j < 8; j++) { v[j] = 0.5f * vth; tc[j] = 0.0f; }

    float o[8];

    #pragma unroll
    for (int j = 0; j < 8; j++) o[j] = bif_step(v[j], tc[j], xs0[j], vth);
    stg256(out + idx, o);

    #pragma unroll
    for (int j = 0; j < 8; j++) o[j] = bif_step(v[j], tc[j], xs1[j], vth);
    stg256(out + idx + (size_t)stepN, o);

    #pragma unroll
    for (int j = 0; j < 8; j++) o[j] = bif_step(v[j], tc[j], xs2[j], vth);
    stg256(out + idx + (size_t)2 * stepN, o);

    #pragma unroll
    for (int j = 0; j < 8; j++) o[j] = bif_step(v[j], tc[j], xs3[j], vth);
    stg256(out + idx + (size_t)3 * stepN, o);
}

extern "C" void kernel_launch(void* const* d_in, const int* in_sizes, int n_in,
                              void* d_out, int out_size) {
    const float* x   = (const float*)d_in[0];   // [T*B, L, D] fp32
    const float* qth = (const float*)d_in[1];   // scalar fp32
    float* out = (float*)d_out;

    int total = in_sizes[0];         // T*B*L*D = 50,331,648
    int stepN = total / TSTEPS;      // B*L*D   = 12,582,912 (divisible by 8)

    int threads = stepN / 8;         // one thread per 8 floats per timestep
    int tpb = 256;
    int blocks = (threads + tpb - 1) / tpb;   // 6144
    st_bif_ms_kernel<<<blocks, tpb>>>(x, qth, out, stepN);
}